// round 4
// baseline (speedup 1.0000x reference)
#include <cuda_runtime.h>

#define B 256
#define R 1152
#define C 10
#define O 16
#define I 8
#define NRC 4          // r-chunks for s_kernel
#define RCH (R / NRC)  // 288

__device__ float g_b[R * C];
__device__ float g_c[R * C];
__device__ float g_v[B * C * O];
__device__ float g_spart[NRC * B * C * O];

__global__ void init_k() {
    int i = blockIdx.x * blockDim.x + threadIdx.x;
    if (i < R * C) g_b[i] = 0.0f;
}

// softmax over routes (axis r) per capsule c. One block per c.
__global__ void softmax_k() {
    const int c = blockIdx.x;
    const int tid = threadIdx.x;
    __shared__ float sm[128];

    float m = -1e30f;
    for (int r = tid; r < R; r += 128) m = fmaxf(m, g_b[r * C + c]);
    sm[tid] = m;
    __syncthreads();
    for (int s = 64; s > 0; s >>= 1) {
        if (tid < s) sm[tid] = fmaxf(sm[tid], sm[tid + s]);
        __syncthreads();
    }
    m = sm[0];
    __syncthreads();

    float sum = 0.0f;
    for (int r = tid; r < R; r += 128) sum += expf(g_b[r * C + c] - m);
    sm[tid] = sum;
    __syncthreads();
    for (int s = 64; s > 0; s >>= 1) {
        if (tid < s) sm[tid] += sm[tid + s];
        __syncthreads();
    }
    float inv = 1.0f / sm[0];

    for (int r = tid; r < R; r += 128)
        g_c[r * C + c] = expf(g_b[r * C + c] - m) * inv;
}

__device__ __forceinline__ float dot8(float4 wa, float4 wb, float4 xa, float4 xb) {
    float t = wa.x * xa.x;
    t = fmaf(wa.y, xa.y, t);
    t = fmaf(wa.z, xa.z, t);
    t = fmaf(wa.w, xa.w, t);
    t = fmaf(wb.x, xb.x, t);
    t = fmaf(wb.y, xb.y, t);
    t = fmaf(wb.z, xb.z, t);
    t = fmaf(wb.w, xb.w, t);
    return t;
}

// s partials: s[b,c,o] = sum_r c[r,c] * (W[r,c,o,:] . x[b,r,:])
// grid: (NRC, B/64, C). block: 256 threads = 16 o x 16 bq, 4 batches per thread.
__global__ void __launch_bounds__(256) s_kernel(const float* __restrict__ x,
                                                const float* __restrict__ W) {
    const int c = blockIdx.z;
    const int rbase = blockIdx.x * RCH;
    const int b0 = blockIdx.y * 64 + (threadIdx.x >> 4) * 4;
    const int o = threadIdx.x & 15;

    __shared__ float csm[RCH];
    for (int t = threadIdx.x; t < RCH; t += 256) csm[t] = g_c[(rbase + t) * C + c];
    __syncthreads();

    const float4* wp  = (const float4*)(W + ((size_t)(rbase * C + c) * O + o) * I);
    const float4* xp0 = (const float4*)(x + ((size_t)(b0 + 0) * R + rbase) * I);
    const float4* xp1 = (const float4*)(x + ((size_t)(b0 + 1) * R + rbase) * I);
    const float4* xp2 = (const float4*)(x + ((size_t)(b0 + 2) * R + rbase) * I);
    const float4* xp3 = (const float4*)(x + ((size_t)(b0 + 3) * R + rbase) * I);

    float a0 = 0.0f, a1 = 0.0f, a2 = 0.0f, a3 = 0.0f;

    for (int rl = 0; rl < RCH; rl++) {
        const float cr = csm[rl];
        const float4 wa = wp[0], wb = wp[1];
        {
            float4 xa = xp0[0], xb = xp0[1];
            a0 = fmaf(cr, dot8(wa, wb, xa, xb), a0);
        }
        {
            float4 xa = xp1[0], xb = xp1[1];
            a1 = fmaf(cr, dot8(wa, wb, xa, xb), a1);
        }
        {
            float4 xa = xp2[0], xb = xp2[1];
            a2 = fmaf(cr, dot8(wa, wb, xa, xb), a2);
        }
        {
            float4 xa = xp3[0], xb = xp3[1];
            a3 = fmaf(cr, dot8(wa, wb, xa, xb), a3);
        }
        wp += (C * O * I) / 4;  // advance one route
        xp0 += 2; xp1 += 2; xp2 += 2; xp3 += 2;
    }

    int base = ((blockIdx.x * B + b0) * C + c) * O + o;
    g_spart[base]             = a0;
    g_spart[base + 1 * C * O] = a1;
    g_spart[base + 2 * C * O] = a2;
    g_spart[base + 3 * C * O] = a3;
}

// reduce partials + squash. v = s^2*s / ((1+s^2)*|s|) == s*|s|/(1+s^2)
__global__ void squash_k(float* __restrict__ out) {
    const int idx = blockIdx.x * 256 + threadIdx.x;  // < B*C*O
    float s = g_spart[idx]
            + g_spart[idx + 1 * B * C * O]
            + g_spart[idx + 2 * B * C * O]
            + g_spart[idx + 3 * B * C * O];
    float v = s * fabsf(s) / (1.0f + s * s);
    float* dst = out ? out : g_v;
    dst[idx] = v;
}

// agreement: g_b[r,c] += (1/B) * sum_b sum_o (W[r,c,o,:].x[b,r,:]) * v[b,c,o]
// grid: (R/32, C). block: 256 threads, thread = batch.
__global__ void __launch_bounds__(256) a_kernel(const float* __restrict__ x,
                                                const float* __restrict__ W) {
    const int rbase = blockIdx.x * 32;
    const int c = blockIdx.y;
    const int tid = threadIdx.x;

    __shared__ float Wsm[32 * 128];   // 16 KB: W[rbase..+32, c, :, :]
    __shared__ float vsm[256 * 17];   // padded: v[b, c, o] at vsm[b*17+o]
    __shared__ float red[32 * 8];

    for (int idx = tid; idx < 32 * 128; idx += 256) {
        int rl = idx >> 7, f = idx & 127;
        Wsm[idx] = W[((size_t)(rbase + rl) * C + c) * (O * I) + f];
    }
    for (int idx = tid; idx < 256 * 16; idx += 256) {
        int b = idx >> 4, o = idx & 15;
        vsm[b * 17 + o] = g_v[((size_t)b * C + c) * O + o];
    }
    __syncthreads();

    const int b = tid;
    const int lane = tid & 31, warp = tid >> 5;
    const float4* xr = (const float4*)(x + ((size_t)b * R + rbase) * I);
    const float* vrow = vsm + b * 17;

    for (int rl = 0; rl < 32; rl++) {
        float4 xa = xr[0], xb = xr[1];
        xr += 2;
        const float4* wrow = (const float4*)(Wsm + rl * 128);
        float part = 0.0f;
#pragma unroll
        for (int o = 0; o < 16; o++) {
            float4 wa = wrow[o * 2], wb = wrow[o * 2 + 1];
            part = fmaf(dot8(wa, wb, xa, xb), vrow[o], part);
        }
#pragma unroll
        for (int off = 16; off; off >>= 1)
            part += __shfl_xor_sync(0xffffffffu, part, off);
        if (lane == 0) red[rl * 8 + warp] = part;
    }
    __syncthreads();

    if (tid < 32) {
        float s = 0.0f;
#pragma unroll
        for (int w = 0; w < 8; w++) s += red[tid * 8 + w];
        g_b[(rbase + tid) * C + c] += s * (1.0f / (float)B);
    }
}

extern "C" void kernel_launch(void* const* d_in, const int* in_sizes, int n_in,
                              void* d_out, int out_size) {
    const float* x = (const float*)d_in[0];
    const float* W = (const float*)d_in[1];
    // defensive: identify by element counts (x: B*R*I, W: R*C*O*I)
    if (n_in >= 2 && in_sizes[0] == R * C * O * I) {
        x = (const float*)d_in[1];
        W = (const float*)d_in[0];
    }

    init_k<<<(R * C + 255) / 256, 256>>>();
    for (int it = 0; it < 3; it++) {
        softmax_k<<<C, 128>>>();
        s_kernel<<<dim3(NRC, B / 64, C), 256>>>(x, W);
        squash_k<<<(B * C * O) / 256, 256>>>(it == 2 ? (float*)d_out : nullptr);
        if (it < 2) a_kernel<<<dim3(R / 32, C), 256>>>(x, W);
    }
}

// round 6
// speedup vs baseline: 3.0329x; 3.0329x over previous
#include <cuda_runtime.h>

#define B 256
#define R 1152
#define C 10
#define O 16
#define I 8
#define K9 (R * I)      // 9216
#define N160 (C * O)    // 160
#define NKS 64          // K-split for gemm1
#define KC (K9 / NKS)   // 144

__device__ float g_b[R * C];
__device__ float g_c[R * C];
__device__ float g_xT[K9 * B];           // xT[k][b]
__device__ float g_Wc[K9 * N160];        // Wc[k][n] = c[r,cap]*W[r,cap,o,i], k=r*8+i, n=cap*16+o
__device__ float g_v[B * N160];          // v[b][n]
__device__ float g_spart[NKS * B * N160];

__global__ void init_k() {
    int i = blockIdx.x * blockDim.x + threadIdx.x;
    if (i < R * C) g_b[i] = 0.0f;
}

// x (B x K9) -> g_xT (K9 x B), tiled transpose
__global__ void transpose_k(const float* __restrict__ x) {
    __shared__ float sm[32][33];
    const int k0 = blockIdx.x * 32, b0 = blockIdx.y * 32;
    const int tx = threadIdx.x, ty = threadIdx.y;
#pragma unroll
    for (int j = 0; j < 32; j += 8)
        sm[ty + j][tx] = x[(size_t)(b0 + ty + j) * K9 + k0 + tx];
    __syncthreads();
#pragma unroll
    for (int j = 0; j < 32; j += 8)
        g_xT[(size_t)(k0 + ty + j) * B + b0 + tx] = sm[tx][ty + j];
}

// softmax over routes (axis r) per capsule c. One block per c.
__global__ void softmax_k() {
    const int c = blockIdx.x;
    const int tid = threadIdx.x;
    __shared__ float sm[128];

    float m = -1e30f;
    for (int r = tid; r < R; r += 128) m = fmaxf(m, g_b[r * C + c]);
    sm[tid] = m;
    __syncthreads();
    for (int s = 64; s > 0; s >>= 1) {
        if (tid < s) sm[tid] = fmaxf(sm[tid], sm[tid + s]);
        __syncthreads();
    }
    m = sm[0];
    __syncthreads();

    float sum = 0.0f;
    for (int r = tid; r < R; r += 128) sum += expf(g_b[r * C + c] - m);
    sm[tid] = sum;
    __syncthreads();
    for (int s = 64; s > 0; s >>= 1) {
        if (tid < s) sm[tid] += sm[tid + s];
        __syncthreads();
    }
    float inv = 1.0f / sm[0];

    for (int r = tid; r < R; r += 128)
        g_c[r * C + c] = expf(g_b[r * C + c] - m) * inv;
}

// Wc[k=(r,i)][n=(c,o)] = c[r,c] * W[r,c,o,i]. One block per route r.
__global__ void __launch_bounds__(256) scale_k(const float* __restrict__ W, int uniform) {
    const int r = blockIdx.x;
    const int tid = threadIdx.x;
    __shared__ float wsm[O * I * C];  // 1280: layout (c,o,i)
    __shared__ float csm[C];

    for (int idx = tid; idx < 1280; idx += 256)
        wsm[idx] = W[(size_t)r * 1280 + idx];
    if (tid < C) csm[tid] = uniform ? (1.0f / (float)R) : g_c[r * C + tid];
    __syncthreads();

    for (int idx = tid; idx < 1280; idx += 256) {
        int i = idx / N160;        // 0..7
        int n = idx - i * N160;    // 0..159
        int c = n >> 4;
        g_Wc[(size_t)r * 1280 + idx] = csm[c] * wsm[n * I + i];
    }
}

// GEMM1 partials: spart[ks][b][n] = sum_{k in chunk} xT[k][b] * Wc[k][n]
// tile 128(b) x 32(n), 128 threads, 8x4 per thread. grid (2, 5, NKS).
__global__ void __launch_bounds__(128) gemm1_k() {
    const int b0 = blockIdx.x * 128, n0 = blockIdx.y * 32;
    const int k0 = blockIdx.z * KC;
    const int tid = threadIdx.x;
    const int tn = tid & 7, tm = tid >> 3;  // tn 0..7 (n), tm 0..15 (b)

    __shared__ float xs[16][128];
    __shared__ float ws[16][32];
    float acc[8][4];
#pragma unroll
    for (int j = 0; j < 8; j++)
#pragma unroll
        for (int l = 0; l < 4; l++) acc[j][l] = 0.0f;

    for (int step = 0; step < KC / 16; step++) {
        const int kb = k0 + step * 16;
#pragma unroll
        for (int j = 0; j < 4; j++) {
            int idx4 = tid + j * 128;            // 0..511
            int row = idx4 >> 5, col4 = idx4 & 31;
            *(float4*)&xs[row][col4 * 4] =
                *(const float4*)(g_xT + (size_t)(kb + row) * B + b0 + col4 * 4);
        }
        {
            int row = tid >> 3, col4 = tid & 7;
            *(float4*)&ws[row][col4 * 4] =
                *(const float4*)(g_Wc + (size_t)(kb + row) * N160 + n0 + col4 * 4);
        }
        __syncthreads();
#pragma unroll
        for (int kk = 0; kk < 16; kk++) {
            float4 x0 = *(float4*)&xs[kk][tm * 8];
            float4 x1 = *(float4*)&xs[kk][tm * 8 + 4];
            float4 w0 = *(float4*)&ws[kk][tn * 4];
            float xv[8] = {x0.x, x0.y, x0.z, x0.w, x1.x, x1.y, x1.z, x1.w};
            float wv[4] = {w0.x, w0.y, w0.z, w0.w};
#pragma unroll
            for (int j = 0; j < 8; j++)
#pragma unroll
                for (int l = 0; l < 4; l++)
                    acc[j][l] = fmaf(xv[j], wv[l], acc[j][l]);
        }
        __syncthreads();
    }

    float* sp = g_spart + (size_t)blockIdx.z * (B * N160);
#pragma unroll
    for (int j = 0; j < 8; j++)
        *(float4*)&sp[(size_t)(b0 + tm * 8 + j) * N160 + n0 + tn * 4] =
            make_float4(acc[j][0], acc[j][1], acc[j][2], acc[j][3]);
}

// reduce partials + squash. v = s*|s|/(1+s^2)
__global__ void squash_k(float* __restrict__ out) {
    const int idx = blockIdx.x * 256 + threadIdx.x;  // < B*N160 = 40960
    float s = 0.0f;
#pragma unroll
    for (int ks = 0; ks < NKS; ks++) s += g_spart[(size_t)ks * (B * N160) + idx];
    float v = s * fabsf(s) / (1.0f + s * s);
    g_v[idx] = v;
    if (out) out[idx] = v;
}

// Agreement fused: G[m=(r,i)][n=(c,o)] = sum_b xT[m][b]*v[b][n], then
// g_b[r,c] += (1/B) * sum_{i,o} G * W[r,c,o,i].
// tile 128(m) x 32(n), 128 threads, 8x4 per thread. grid (72, 5).
__global__ void __launch_bounds__(128) gemm2_k(const float* __restrict__ W) {
    const int m0 = blockIdx.x * 128, n0 = blockIdx.y * 32;
    const int tid = threadIdx.x;
    const int tn = tid & 7, tm = tid >> 3;

    __shared__ float as[16][132];  // [kk=b][m], padded
    __shared__ float vs[16][32];
    float acc[8][4];
#pragma unroll
    for (int j = 0; j < 8; j++)
#pragma unroll
        for (int l = 0; l < 4; l++) acc[j][l] = 0.0f;

    for (int step = 0; step < B / 16; step++) {
        const int bb = step * 16;
#pragma unroll
        for (int j = 0; j < 4; j++) {
            int idx4 = tid + j * 128;          // 0..511
            int ml = idx4 >> 2, kk4 = idx4 & 3;
            float4 v4 = *(const float4*)(g_xT + (size_t)(m0 + ml) * B + bb + kk4 * 4);
            as[kk4 * 4 + 0][ml] = v4.x;
            as[kk4 * 4 + 1][ml] = v4.y;
            as[kk4 * 4 + 2][ml] = v4.z;
            as[kk4 * 4 + 3][ml] = v4.w;
        }
        {
            int row = tid >> 3, col4 = tid & 7;
            *(float4*)&vs[row][col4 * 4] =
                *(const float4*)(g_v + (size_t)(bb + row) * N160 + n0 + col4 * 4);
        }
        __syncthreads();
#pragma unroll
        for (int kk = 0; kk < 16; kk++) {
            float4 x0 = *(float4*)&as[kk][tm * 8];
            float4 x1 = *(float4*)&as[kk][tm * 8 + 4];
            float4 w0 = *(float4*)&vs[kk][tn * 4];
            float xv[8] = {x0.x, x0.y, x0.z, x0.w, x1.x, x1.y, x1.z, x1.w};
            float wv[4] = {w0.x, w0.y, w0.z, w0.w};
#pragma unroll
            for (int j = 0; j < 8; j++)
#pragma unroll
                for (int l = 0; l < 4; l++)
                    acc[j][l] = fmaf(xv[j], wv[l], acc[j][l]);
        }
        __syncthreads();
    }

    // Epilogue: each thread's 8 m span exactly one r (i = 0..7), 4 n within one c.
    const int r = (m0 >> 3) + tm;            // m0 + tm*8 -> r, i=j
    const int nb = n0 + tn * 4;
    const int c = nb >> 4, o0 = nb & 15;
    const float* wrc = W + ((size_t)(r * C + c) * O) * I;
    float part = 0.0f;
#pragma unroll
    for (int j = 0; j < 8; j++)
#pragma unroll
        for (int l = 0; l < 4; l++)
            part = fmaf(acc[j][l], wrc[(o0 + l) * I + j], part);

    __shared__ float red[32][4];
    const int slot = tm * 2 + (tn >> 2);     // (r_local, c_local) -> 0..31
    red[slot][tn & 3] = part;
    __syncthreads();
    if (tid < 32) {
        float s = red[tid][0] + red[tid][1] + red[tid][2] + red[tid][3];
        int rr = (m0 >> 3) + (tid >> 1);
        int cc = (n0 >> 4) + (tid & 1);
        g_b[rr * C + cc] += s * (1.0f / (float)B);
    }
}

extern "C" void kernel_launch(void* const* d_in, const int* in_sizes, int n_in,
                              void* d_out, int out_size) {
    const float* x = (const float*)d_in[0];
    const float* W = (const float*)d_in[1];
    if (n_in >= 2 && in_sizes[0] == R * C * O * I) {
        x = (const float*)d_in[1];
        W = (const float*)d_in[0];
    }

    init_k<<<(R * C + 255) / 256, 256>>>();
    transpose_k<<<dim3(K9 / 32, B / 32), dim3(32, 8)>>>(x);

    for (int it = 0; it < 3; it++) {
        if (it > 0) softmax_k<<<C, 128>>>();
        scale_k<<<R, 256>>>(W, it == 0 ? 1 : 0);
        gemm1_k<<<dim3(B / 128, N160 / 32, NKS), 128>>>();
        squash_k<<<(B * N160) / 256, 256>>>(it == 2 ? (float*)d_out : nullptr);
        if (it < 2) gemm2_k<<<dim3(K9 / 128, N160 / 32), 128>>>(W);
    }
}